// round 15
// baseline (speedup 1.0000x reference)
#include <cuda_runtime.h>
#include <cuda_bf16.h>
#include <math.h>

#define B_  2
#define S_  2048
#define D_  512
#define H_  8
#define HD_ 64
#define NBH 16   // B_*H_

// Scratch (static __device__ — no allocations allowed)
__device__ float g_q[(size_t)NBH * S_ * HD_];
__device__ float g_k[(size_t)NBH * S_ * HD_];
__device__ float g_v[(size_t)NBH * S_ * HD_];
__device__ __nv_bfloat16 g_qh[(size_t)NBH * S_ * HD_];
__device__ __nv_bfloat16 g_kh[(size_t)NBH * S_ * HD_];
__device__ float g_fi[(size_t)NBH * S_];
__device__ float g_ctx[(size_t)B_ * S_ * D_];
__device__ uint2 g_wpP[(size_t)512 * 512];   // w_proj packed tf32 hi/lo

__device__ __forceinline__ void tf32split(float x, unsigned& hi, unsigned& lo)
{
    unsigned h;
    asm("cvt.rna.tf32.f32 %0, %1;" : "=r"(h) : "f"(x));
    float lf = x - __uint_as_float(h);
    unsigned l;
    asm("cvt.rna.tf32.f32 %0, %1;" : "=r"(l) : "f"(lf));
    hi = h; lo = l;
}

// ---------------------------------------------------------------------------
__global__ void pack_wp(const float* __restrict__ src)
{
    for (int idx = blockIdx.x * blockDim.x + threadIdx.x; idx < 512 * 512;
         idx += gridDim.x * blockDim.x) {
        unsigned hi, lo;
        tf32split(src[idx], hi, lo);
        g_wpP[idx] = make_uint2(hi, lo);
    }
}

// ---------------------------------------------------------------------------
// R8-proven pipelined fp32 GEMM (FROZEN numerics: k-ascending single-acc
// FFMA chain). mode 1: QKV epilogue -> q/k/v head layout (+ bf16 q,k planes).
// NEW: optional background zero-fill of the attn output plane (zfill) —
// this kernel runs at DRAM=1.1%, so the 268MB fill drains for free under
// the FFMA mainloop instead of throttling the L1TEX-bound attn kernel.
// ---------------------------------------------------------------------------
__global__ __launch_bounds__(256)
void sgemm_pipe(const float* __restrict__ A, const float* __restrict__ Bm,
                const float* __restrict__ bias, float* __restrict__ C,
                int M, int N, int K, int mode, float* __restrict__ zfill)
{
    // background fill: fire-and-forget stores, drained under the GEMM
    if (zfill) {
        const size_t total4 = (size_t)NBH * S_ * S_ / 4;   // 16.7M float4
        float4 z4 = make_float4(0.f, 0.f, 0.f, 0.f);
        float4* zp = (float4*)zfill;
        size_t stride = (size_t)gridDim.x * blockDim.x;
        for (size_t i = (size_t)blockIdx.x * blockDim.x + threadIdx.x;
             i < total4; i += stride)
            zp[i] = z4;
    }

    __shared__ float As[16][132];   // transposed: As[k][m], padded
    __shared__ float Bs[16][64];

    const int tid = threadIdx.x;
    const int tx = tid & 15, ty = tid >> 4;
    const int m0 = blockIdx.y << 7, n0 = blockIdx.x << 6;

    const int arow = tid >> 1;            // 0..127
    const int ac   = (tid & 1) << 3;      // k base 0 or 8
    const int brow = tid >> 4;            // 0..15
    const int bc   = (tid & 15) << 2;     // 0..60

    const float* Ap = A  + (size_t)(m0 + arow) * K + ac;
    const float* Bp = Bm + (size_t)brow * N + n0 + bc;

    float acc[8][4];
#pragma unroll
    for (int i = 0; i < 8; ++i)
#pragma unroll
        for (int j = 0; j < 4; ++j) acc[i][j] = 0.f;

    float4 pa0 = *(const float4*)(Ap);
    float4 pa1 = *(const float4*)(Ap + 4);
    float4 pb  = *(const float4*)(Bp);

    const int ty8 = ty << 3, tx4 = tx << 2;

    for (int k0 = 0; k0 < K; k0 += 16) {
        __syncthreads();
        As[ac + 0][arow] = pa0.x;
        As[ac + 1][arow] = pa0.y;
        As[ac + 2][arow] = pa0.z;
        As[ac + 3][arow] = pa0.w;
        As[ac + 4][arow] = pa1.x;
        As[ac + 5][arow] = pa1.y;
        As[ac + 6][arow] = pa1.z;
        As[ac + 7][arow] = pa1.w;
        *(float4*)&Bs[brow][bc] = pb;
        __syncthreads();
        if (k0 + 16 < K) {
            pa0 = *(const float4*)(Ap + k0 + 16);
            pa1 = *(const float4*)(Ap + k0 + 20);
            pb  = *(const float4*)(Bp + (size_t)(k0 + 16) * N);
        }
#pragma unroll
        for (int kk = 0; kk < 16; ++kk) {
            float4 a0 = *(const float4*)&As[kk][ty8];
            float4 a1 = *(const float4*)&As[kk][ty8 + 4];
            float4 bv = *(const float4*)&Bs[kk][tx4];
            float am[8] = {a0.x,a0.y,a0.z,a0.w,a1.x,a1.y,a1.z,a1.w};
            float bn[4] = {bv.x,bv.y,bv.z,bv.w};
#pragma unroll
            for (int i = 0; i < 8; ++i)
#pragma unroll
                for (int j = 0; j < 4; ++j)
                    acc[i][j] += am[i] * bn[j];
        }
    }

    const int n_base = n0 + tx4;
    if (mode != 1) {
        const float* bp2 = bias + n_base;
        float4 bb = make_float4(bp2[0], bp2[1], bp2[2], bp2[3]);
#pragma unroll
        for (int i = 0; i < 8; ++i) {
            int m = m0 + ty8 + i;
            float4 v = make_float4(acc[i][0] + bb.x, acc[i][1] + bb.y,
                                   acc[i][2] + bb.z, acc[i][3] + bb.w);
            *(float4*)(C + (size_t)m * N + n_base) = v;
        }
    } else {
        int t3 = n_base >> 9;            // 0:q 1:k 2:v
        int cc = n_base & 511;
        int h = cc >> 6, hd = cc & 63;
        float* dst = (t3 == 0) ? g_q : (t3 == 1) ? g_k : g_v;
        __nv_bfloat16* dsth = (t3 == 0) ? g_qh : (t3 == 1) ? g_kh : nullptr;
        const float* bp2 = bias + n_base;
        float4 bb = make_float4(bp2[0], bp2[1], bp2[2], bp2[3]);
#pragma unroll
        for (int i = 0; i < 8; ++i) {
            int m = m0 + ty8 + i;
            int b = m >> 11, s = m & 2047;
            size_t off = (((size_t)(b * H_ + h) * S_) + s) * HD_ + hd;
            float v0 = acc[i][0] + bb.x, v1 = acc[i][1] + bb.y;
            float v2 = acc[i][2] + bb.z, v3 = acc[i][3] + bb.w;
            *(float4*)(dst + off) = make_float4(v0, v1, v2, v3);
            if (dsth) {
                unsigned p0 = (unsigned)__bfloat16_as_ushort(__float2bfloat16_rn(v0)) |
                              ((unsigned)__bfloat16_as_ushort(__float2bfloat16_rn(v1)) << 16);
                unsigned p1 = (unsigned)__bfloat16_as_ushort(__float2bfloat16_rn(v2)) |
                              ((unsigned)__bfloat16_as_ushort(__float2bfloat16_rn(v3)) << 16);
                *(uint2*)(dsth + off) = make_uint2(p0, p1);
            }
        }
    }
}

// ---------------------------------------------------------------------------
__global__ void fi_kernel()
{
    int i = blockIdx.x * blockDim.x + threadIdx.x;
    if (i >= NBH * S_) return;
    const float4* q = (const float4*)(g_q + (size_t)i * HD_);
    float s = 0.f;
#pragma unroll
    for (int u = 0; u < 16; ++u) {
        float4 v = q[u];
        s += v.x + v.y + v.z + v.w;
    }
    float mval = s * (1.f / 64.f);
    g_fi[i] = 1.f / (1.f + expf(-mval));
}

// ---------------------------------------------------------------------------
__device__ __forceinline__ void ldsm4(unsigned* r, unsigned saddr)
{
    asm volatile("ldmatrix.sync.aligned.m8n8.x4.shared.b16 {%0,%1,%2,%3}, [%4];"
                 : "=r"(r[0]), "=r"(r[1]), "=r"(r[2]), "=r"(r[3]) : "r"(saddr));
}

__device__ __forceinline__ void mma_bf16(float* c, const unsigned* a, const unsigned* b)
{
    asm volatile("mma.sync.aligned.m16n8k16.row.col.f32.bf16.bf16.f32 "
                 "{%0,%1,%2,%3},{%4,%5,%6,%7},{%8,%9},{%0,%1,%2,%3};"
                 : "+f"(c[0]), "+f"(c[1]), "+f"(c[2]), "+f"(c[3])
                 : "r"(a[0]), "r"(a[1]), "r"(a[2]), "r"(a[3]),
                   "r"(b[0]), "r"(b[1]));
}

// Sequential d-ascending single-accumulator FFMA chain (LOAD-BEARING: exact
// tie resolution matching the reference — do not change).
__device__ __forceinline__ float dot64_seq(const float* __restrict__ a,
                                           const float* __restrict__ b)
{
    const float4* A4 = (const float4*)a;
    const float4* B4 = (const float4*)b;
    float s = 0.f;
#pragma unroll
    for (int i = 0; i < 16; ++i) {
        float4 x = A4[i], y = B4[i];
        s = __fmaf_rn(x.x, y.x, s);
        s = __fmaf_rn(x.y, y.y, s);
        s = __fmaf_rn(x.z, y.z, s);
        s = __fmaf_rn(x.w, y.w, s);
    }
    return s;
}

// sorted-desc top-5 insert (pre-checked by caller: v > tv[4])
__device__ __forceinline__ void ins5(float* tv, int* ti, float v, int idx)
{
    tv[4] = v; ti[4] = idx;
#pragma unroll
    for (int u = 4; u > 0; --u) {
        if (tv[u] > tv[u - 1]) {
            float a = tv[u]; tv[u] = tv[u - 1]; tv[u - 1] = a;
            int   b = ti[u]; ti[u] = ti[u - 1]; ti[u - 1] = b;
        }
    }
}

// ---------------------------------------------------------------------------
// R11-proven attention (best measured: 189.7us) WITHOUT the zero-fill loop —
// the fill now rides free inside the DRAM-idle QKV GEMM.
// Tensor-core approx scores, in-register per-lane top-5 per row ->
// 20 candidates/row -> EXACT dot64_seq rescore -> top-5 -> window mask ->
// softmax -> attn scatter + sparse ctx.
// ---------------------------------------------------------------------------
__global__ __launch_bounds__(256)
void attn_mma3(float* __restrict__ out_attn)
{
    __shared__ __align__(16) unsigned char shK[16384];  // 128 keys x 128B swizzled
    __shared__ float mbv[128 * 20];
    __shared__ int   mbi[128 * 20];
    __shared__ float spw[128][5];
    __shared__ unsigned short spidx[128][5];

    const int tid = threadIdx.x;
    const int w = tid >> 5, lane = tid & 31;
    const int bh = blockIdx.y;
    const int qblk = blockIdx.x << 7;

    const __nv_bfloat16* qh = g_qh + ((size_t)bh * S_ + qblk) * HD_;
    const __nv_bfloat16* kh = g_kh + (size_t)bh * S_ * HD_;

    // ---- A fragments for this warp's 16 rows (verified layout) ----
    unsigned Af[4][4];
    {
        int r = (w << 4) + (lane >> 2);
        int c0 = (lane & 3) << 1;
#pragma unroll
        for (int ks = 0; ks < 4; ++ks) {
            Af[ks][0] = *(const unsigned*)(qh + (size_t)r * 64 + ks * 16 + c0);
            Af[ks][1] = *(const unsigned*)(qh + (size_t)(r + 8) * 64 + ks * 16 + c0);
            Af[ks][2] = *(const unsigned*)(qh + (size_t)r * 64 + ks * 16 + c0 + 8);
            Af[ks][3] = *(const unsigned*)(qh + (size_t)(r + 8) * 64 + ks * 16 + c0 + 8);
        }
    }

    float tvA[5], tvB[5]; int tiA[5], tiB[5];
#pragma unroll
    for (int i = 0; i < 5; ++i) {
        tvA[i] = -INFINITY; tvB[i] = -INFINITY; tiA[i] = 0; tiB[i] = 0;
    }

    const int mykey = tid >> 1;
    const int cbase = (tid & 1) << 2;
    uint4 pf[4];
#pragma unroll
    for (int j = 0; j < 4; ++j)
        pf[j] = *(const uint4*)((const char*)kh + (size_t)mykey * 128 + (cbase + j) * 16);

    const int m = lane >> 3, ii = lane & 7;

    for (int kt = 0; kt < 16; ++kt) {
        __syncthreads();
#pragma unroll
        for (int j = 0; j < 4; ++j)
            *(uint4*)(shK + mykey * 128 + (((cbase + j) ^ (mykey & 7)) << 4)) = pf[j];
        __syncthreads();
        if (kt < 15) {
            const char* src = (const char*)kh + ((size_t)(kt + 1) * 128 + mykey) * 128;
#pragma unroll
            for (int j = 0; j < 4; ++j)
                pf[j] = *(const uint4*)(src + (cbase + j) * 16);
        }

#pragma unroll
        for (int np = 0; np < 8; ++np) {
            float c[8];
#pragma unroll
            for (int q = 0; q < 8; ++q) c[q] = 0.f;
#pragma unroll
            for (int ks = 0; ks < 4; ++ks) {
                int keyy = (np << 4) + ((m >> 1) << 3) + ii;
                int ch = (ks << 1) + (m & 1);
                unsigned br[4];
                unsigned sa = (unsigned)__cvta_generic_to_shared(
                    shK + keyy * 128 + ((ch ^ (keyy & 7)) << 4));
                ldsm4(br, sa);
                mma_bf16(c, Af[ks], br);
                mma_bf16(c + 4, Af[ks], br + 2);
            }
            int kb = (kt << 7) + (np << 4) + ((lane & 3) << 1);
            if (c[0] > tvA[4]) ins5(tvA, tiA, c[0], kb);
            if (c[1] > tvA[4]) ins5(tvA, tiA, c[1], kb + 1);
            if (c[2] > tvB[4]) ins5(tvB, tiB, c[2], kb);
            if (c[3] > tvB[4]) ins5(tvB, tiB, c[3], kb + 1);
            if (c[4] > tvA[4]) ins5(tvA, tiA, c[4], kb + 8);
            if (c[5] > tvA[4]) ins5(tvA, tiA, c[5], kb + 9);
            if (c[6] > tvB[4]) ins5(tvB, tiB, c[6], kb + 8);
            if (c[7] > tvB[4]) ins5(tvB, tiB, c[7], kb + 9);
        }
    }

    // ---- dump 5 candidates per (row, lane-group) to smem ----
    {
        int rowA = (w << 4) + (lane >> 2);
        int rowB = rowA + 8;
        int l = lane & 3;
#pragma unroll
        for (int u = 0; u < 5; ++u) {
            mbv[rowA * 20 + l * 5 + u] = tvA[u];
            mbi[rowA * 20 + l * 5 + u] = tiA[u];
            mbv[rowB * 20 + l * 5 + u] = tvB[u];
            mbi[rowB * 20 + l * 5 + u] = tiB[u];
        }
    }
    __syncthreads();

    // ---- exact sequential-fp32 rescore: 2 threads/row, 10 candidates each ----
    const float* kbase = g_k + (size_t)bh * S_ * HD_;
    {
        const int q_own = tid >> 1, par = tid & 1;
        const float* qrow = g_q + ((size_t)bh * S_ + qblk + q_own) * HD_;
#pragma unroll
        for (int i = 0; i < 10; ++i) {
            int slot = q_own * 20 + (par * 2 + (i >= 5 ? 1 : 0)) * 5 + (i % 5);
            mbv[slot] = dot64_seq(qrow, kbase + (size_t)mbi[slot] * HD_);
        }
    }
    __syncthreads();

    // ---- per-row merge of 20, exact top-5, mask, softmax, scatter ----
    if (tid < 128) {
        const int q = tid;
        const int grow = qblk + q;
        float v20[20]; int k20[20];
#pragma unroll
        for (int i = 0; i < 20; ++i) { v20[i] = mbv[q * 20 + i]; k20[i] = mbi[q * 20 + i]; }
#pragma unroll
        for (int s = 0; s < 5; ++s)
#pragma unroll
            for (int i = 19; i > s; --i)
                if (v20[i] > v20[i - 1]) {
                    float a = v20[i]; v20[i] = v20[i - 1]; v20[i - 1] = a;
                    int   b = k20[i]; k20[i] = k20[i - 1]; k20[i - 1] = b;
                }

        const float* qrow = g_q + ((size_t)bh * S_ + grow) * HD_;
        bool kp[5];
#pragma unroll
        for (int i = 0; i < 5; ++i) {
            int c = k20[i];
            int mn = min(grow, c), mx = max(grow, c);
            int ow = mn & ~1; if (ow > 2044) ow = 2044;
            bool keep = true;
            if (mx <= ow + 3) {
                float st0 = dot64_seq(qrow, kbase + (size_t)(ow + 0) * HD_);
                float st1 = dot64_seq(qrow, kbase + (size_t)(ow + 1) * HD_);
                float st2 = dot64_seq(qrow, kbase + (size_t)(ow + 2) * HD_);
                float st3 = dot64_seq(qrow, kbase + (size_t)(ow + 3) * HD_);
                float mn01 = fminf(st0, st1), mx01 = fmaxf(st0, st1);
                float mn23 = fminf(st2, st3), mx23 = fmaxf(st2, st3);
                float thr = fminf(fmaxf(mn01, mn23), fminf(mx01, mx23));
                int ci = c - ow;
                float cv = (ci == 0) ? st0 : (ci == 1) ? st1 : (ci == 2) ? st2 : st3;
                keep = (cv >= thr);
            }
            kp[i] = keep;
        }

        float sm = -INFINITY;
#pragma unroll
        for (int i = 0; i < 5; ++i) if (kp[i]) sm = fmaxf(sm, v20[i]);
        sm *= 0.125f;
        float p[5]; float sum = 0.f;
#pragma unroll
        for (int i = 0; i < 5; ++i) {
            p[i] = kp[i] ? expf(v20[i] * 0.125f - sm) : 0.f;
            sum += p[i];
        }
        float inv = 1.f / sum;
#pragma unroll
        for (int i = 0; i < 5; ++i) {
            if (kp[i]) {
                float pi = p[i] * inv;
                int c = k20[i];
                if (out_attn) out_attn[((size_t)bh * S_ + grow) * S_ + c] = pi;
                spw[q][i] = pi * g_fi[(size_t)bh * S_ + c];
                spidx[q][i] = (unsigned short)c;
            } else {
                spw[q][i] = 0.f;
                spidx[q][i] = 0;
            }
        }
    }
    __syncthreads();

    // ---- sparse ctx: 2 threads/row, 32 dims each ----
    {
        const int row = tid >> 1;
        const int h0 = (tid & 1) << 5;
        float4 a[8];
#pragma unroll
        for (int j = 0; j < 8; ++j) a[j] = make_float4(0.f, 0.f, 0.f, 0.f);
        const float* vb = g_v + (size_t)bh * S_ * HD_;
#pragma unroll
        for (int i = 0; i < 5; ++i) {
            float wv = spw[row][i];
            int c = spidx[row][i];
            const float4* vr = (const float4*)(vb + (size_t)c * 64 + h0);
#pragma unroll
            for (int j = 0; j < 8; ++j) {
                float4 vv = vr[j];
                a[j].x += wv * vv.x; a[j].y += wv * vv.y;
                a[j].z += wv * vv.z; a[j].w += wv * vv.w;
            }
        }
        int b = bh >> 3, hh = bh & 7;
        float* dp = g_ctx + ((size_t)(b * S_) + qblk + row) * D_ + (hh << 6) + h0;
#pragma unroll
        for (int j = 0; j < 8; ++j) ((float4*)dp)[j] = a[j];
    }
}

// ---------------------------------------------------------------------------
// 3xTF32 output projection: out = g_ctx @ w_proj + bias.
// A (ctx) fp32, split in-loop; B preconverted (g_wpP).
// ---------------------------------------------------------------------------
__device__ __forceinline__ void mma_tf32(float* c, const unsigned* a, const unsigned* b)
{
    asm volatile("mma.sync.aligned.m16n8k8.row.col.f32.tf32.tf32.f32 "
                 "{%0,%1,%2,%3},{%4,%5,%6,%7},{%8,%9},{%0,%1,%2,%3};"
                 : "+f"(c[0]), "+f"(c[1]), "+f"(c[2]), "+f"(c[3])
                 : "r"(a[0]), "r"(a[1]), "r"(a[2]), "r"(a[3]),
                   "r"(b[0]), "r"(b[1]));
}

__global__ __launch_bounds__(256)
void proj_tf32(const float* __restrict__ bias, float* __restrict__ C)
{
    __shared__ float As[128 * 36];   // [m][k] fp32, pad 36
    __shared__ uint2 Bs[32 * 72];    // [k][n] packed hi/lo, pad 72

    const int tid = threadIdx.x;
    const int lane = tid & 31, w = tid >> 5;
    const int wm = w >> 1, wn = w & 1;
    const int m0 = blockIdx.y << 7, n0 = blockIdx.x << 6;
    const int gr = lane >> 2, gc = lane & 3;

    float acc[2][4][4];
#pragma unroll
    for (int a = 0; a < 2; ++a)
#pragma unroll
        for (int b = 0; b < 4; ++b)
#pragma unroll
            for (int cj = 0; cj < 4; ++cj) acc[a][b][cj] = 0.f;

    const int arow = tid >> 1, ak = (tid & 1) << 4;
    const int brow = tid >> 3, bn = (tid & 7) << 3;

    for (int kc = 0; kc < 512; kc += 32) {
        __syncthreads();
        {
            const float* Ap = g_ctx + (size_t)(m0 + arow) * 512 + kc + ak;
            *(float4*)&As[arow * 36 + ak + 0]  = *(const float4*)(Ap);
            *(float4*)&As[arow * 36 + ak + 4]  = *(const float4*)(Ap + 4);
            *(float4*)&As[arow * 36 + ak + 8]  = *(const float4*)(Ap + 8);
            *(float4*)&As[arow * 36 + ak + 12] = *(const float4*)(Ap + 12);
            const uint4* bg = (const uint4*)(g_wpP + (size_t)(kc + brow) * 512 + n0 + bn);
            uint4* bs = (uint4*)(Bs + brow * 72 + bn);
            bs[0] = bg[0]; bs[1] = bg[1]; bs[2] = bg[2]; bs[3] = bg[3];
        }
        __syncthreads();

#pragma unroll
        for (int kk = 0; kk < 4; ++kk) {
            unsigned ah[2][4], al[2][4];
#pragma unroll
            for (int mt = 0; mt < 2; ++mt) {
                int mrow = (wm << 5) + (mt << 4);
                float a_0 = As[(mrow + gr) * 36 + (kk << 3) + gc];
                float a_1 = As[(mrow + gr + 8) * 36 + (kk << 3) + gc];
                float a_2 = As[(mrow + gr) * 36 + (kk << 3) + gc + 4];
                float a_3 = As[(mrow + gr + 8) * 36 + (kk << 3) + gc + 4];
                tf32split(a_0, ah[mt][0], al[mt][0]);
                tf32split(a_1, ah[mt][1], al[mt][1]);
                tf32split(a_2, ah[mt][2], al[mt][2]);
                tf32split(a_3, ah[mt][3], al[mt][3]);
            }
            unsigned bhv[4][2], blv[4][2];
#pragma unroll
            for (int nt = 0; nt < 4; ++nt) {
                int ncol = (wn << 5) + (nt << 3) + gr;
                uint2 b0 = Bs[((kk << 3) + gc) * 72 + ncol];
                uint2 b1 = Bs[((kk << 3) + gc + 4) * 72 + ncol];
                bhv[nt][0] = b0.x; blv[nt][0] = b0.y;
                bhv[nt][1] = b1.x; blv[nt][1] = b1.y;
            }
#pragma unroll
            for (int mt = 0; mt < 2; ++mt)
#pragma unroll
                for (int nt = 0; nt < 4; ++nt) {
                    mma_tf32(acc[mt][nt], al[mt], bhv[nt]);   // lo*hi
                    mma_tf32(acc[mt][nt], ah[mt], blv[nt]);   // hi*lo
                    mma_tf32(acc[mt][nt], ah[mt], bhv[nt]);   // hi*hi
                }
        }
    }

#pragma unroll
    for (int mt = 0; mt < 2; ++mt)
#pragma unroll
        for (int nt = 0; nt < 4; ++nt) {
            int row = m0 + (wm << 5) + (mt << 4) + gr;
            int col = n0 + (wn << 5) + (nt << 3) + (gc << 1);
            float b0v = bias[col], b1v = bias[col + 1];
            *(float2*)(C + (size_t)row * 512 + col) =
                make_float2(acc[mt][nt][0] + b0v, acc[mt][nt][1] + b1v);
            *(float2*)(C + (size_t)(row + 8) * 512 + col) =
                make_float2(acc[mt][nt][2] + b0v, acc[mt][nt][3] + b1v);
        }
}

// ---------------------------------------------------------------------------
extern "C" void kernel_launch(void* const* d_in, const int* in_sizes, int n_in,
                              void* d_out, int out_size)
{
    const float* x      = (const float*)d_in[0];
    const float* w_qkv  = (const float*)d_in[1];
    const float* b_qkv  = (const float*)d_in[2];
    const float* w_proj = (const float*)d_in[3];
    const float* b_proj = (const float*)d_in[4];
    float* out = (float*)d_out;

    const size_t nproj = (size_t)B_ * S_ * D_;
    const size_t nattn = (size_t)NBH * S_ * S_;
    float* out_attn = ((size_t)out_size >= nproj + nattn) ? (out + nproj) : nullptr;

    // 0) pack w_proj to tf32 hi/lo
    pack_wp<<<256, 256>>>(w_proj);
    // 1) fused QKV projection (FROZEN fp32 numerics) + background zero-fill
    //    of the attn plane (this kernel's DRAM is otherwise idle)
    sgemm_pipe<<<dim3(24, 32), 256>>>(x, w_qkv, b_qkv, nullptr,
                                      B_ * S_, 3 * D_, D_, 1, out_attn);
    // 2) feature importance per (b,h,s)
    fi_kernel<<<128, 256>>>();
    // 3) tensor-core scores / exact top-5 / mask / softmax / sparse ctx
    //    (no fill — best-measured R11 variant)
    attn_mma3<<<dim3(S_ / 128, NBH), 256>>>(out_attn);
    // 4) output projection (3xTF32; B preconverted)
    proj_tf32<<<dim3(8, 32), 256>>>(b_proj, out);
}

// round 16
// speedup vs baseline: 3.0732x; 3.0732x over previous
#include <cuda_runtime.h>
#include <cuda_bf16.h>
#include <math.h>

#define B_  2
#define S_  2048
#define D_  512
#define H_  8
#define HD_ 64
#define NBH 16   // B_*H_

// Scratch (static __device__ — no allocations allowed)
__device__ float g_q[(size_t)NBH * S_ * HD_];
__device__ float g_k[(size_t)NBH * S_ * HD_];
__device__ float g_v[(size_t)NBH * S_ * HD_];
__device__ __nv_bfloat16 g_qh[(size_t)NBH * S_ * HD_];
__device__ __nv_bfloat16 g_kh[(size_t)NBH * S_ * HD_];
__device__ float g_fi[(size_t)NBH * S_];
__device__ float g_ctx[(size_t)B_ * S_ * D_];
__device__ uint2 g_wpP[(size_t)512 * 512];   // w_proj packed tf32 hi/lo

__device__ __forceinline__ void tf32split(float x, unsigned& hi, unsigned& lo)
{
    unsigned h;
    asm("cvt.rna.tf32.f32 %0, %1;" : "=r"(h) : "f"(x));
    float lf = x - __uint_as_float(h);
    unsigned l;
    asm("cvt.rna.tf32.f32 %0, %1;" : "=r"(l) : "f"(lf));
    hi = h; lo = l;
}

// ---------------------------------------------------------------------------
__global__ void pack_wp(const float* __restrict__ src)
{
    for (int idx = blockIdx.x * blockDim.x + threadIdx.x; idx < 512 * 512;
         idx += gridDim.x * blockDim.x) {
        unsigned hi, lo;
        tf32split(src[idx], hi, lo);
        g_wpP[idx] = make_uint2(hi, lo);
    }
}

// ---------------------------------------------------------------------------
// R8-proven pipelined fp32 GEMM (FROZEN numerics: k-ascending single-acc
// FFMA chain). mode 1: QKV epilogue -> q/k/v head layout (+ bf16 q,k planes).
// Background zero-fill of the attn plane rides under the FFMA mainloop.
// FIXED vs R15: fill stride now linearizes the FULL 2-D grid (was using
// blockIdx.x only -> 32x duplicated writes -> 8.6GB of stores).
// ---------------------------------------------------------------------------
__global__ __launch_bounds__(256)
void sgemm_pipe(const float* __restrict__ A, const float* __restrict__ Bm,
                const float* __restrict__ bias, float* __restrict__ C,
                int M, int N, int K, int mode, float* __restrict__ zfill)
{
    // background fill: each element written exactly once across the 2-D grid
    if (zfill) {
        const size_t total4 = (size_t)NBH * S_ * S_ / 4;   // 16.7M float4
        float4 z4 = make_float4(0.f, 0.f, 0.f, 0.f);
        float4* zp = (float4*)zfill;
        size_t bid = (size_t)blockIdx.y * gridDim.x + blockIdx.x;
        size_t stride = (size_t)gridDim.x * gridDim.y * blockDim.x;
        for (size_t i = bid * blockDim.x + threadIdx.x; i < total4; i += stride)
            zp[i] = z4;
    }

    __shared__ float As[16][132];   // transposed: As[k][m], padded
    __shared__ float Bs[16][64];

    const int tid = threadIdx.x;
    const int tx = tid & 15, ty = tid >> 4;
    const int m0 = blockIdx.y << 7, n0 = blockIdx.x << 6;

    const int arow = tid >> 1;            // 0..127
    const int ac   = (tid & 1) << 3;      // k base 0 or 8
    const int brow = tid >> 4;            // 0..15
    const int bc   = (tid & 15) << 2;     // 0..60

    const float* Ap = A  + (size_t)(m0 + arow) * K + ac;
    const float* Bp = Bm + (size_t)brow * N + n0 + bc;

    float acc[8][4];
#pragma unroll
    for (int i = 0; i < 8; ++i)
#pragma unroll
        for (int j = 0; j < 4; ++j) acc[i][j] = 0.f;

    float4 pa0 = *(const float4*)(Ap);
    float4 pa1 = *(const float4*)(Ap + 4);
    float4 pb  = *(const float4*)(Bp);

    const int ty8 = ty << 3, tx4 = tx << 2;

    for (int k0 = 0; k0 < K; k0 += 16) {
        __syncthreads();
        As[ac + 0][arow] = pa0.x;
        As[ac + 1][arow] = pa0.y;
        As[ac + 2][arow] = pa0.z;
        As[ac + 3][arow] = pa0.w;
        As[ac + 4][arow] = pa1.x;
        As[ac + 5][arow] = pa1.y;
        As[ac + 6][arow] = pa1.z;
        As[ac + 7][arow] = pa1.w;
        *(float4*)&Bs[brow][bc] = pb;
        __syncthreads();
        if (k0 + 16 < K) {
            pa0 = *(const float4*)(Ap + k0 + 16);
            pa1 = *(const float4*)(Ap + k0 + 20);
            pb  = *(const float4*)(Bp + (size_t)(k0 + 16) * N);
        }
#pragma unroll
        for (int kk = 0; kk < 16; ++kk) {
            float4 a0 = *(const float4*)&As[kk][ty8];
            float4 a1 = *(const float4*)&As[kk][ty8 + 4];
            float4 bv = *(const float4*)&Bs[kk][tx4];
            float am[8] = {a0.x,a0.y,a0.z,a0.w,a1.x,a1.y,a1.z,a1.w};
            float bn[4] = {bv.x,bv.y,bv.z,bv.w};
#pragma unroll
            for (int i = 0; i < 8; ++i)
#pragma unroll
                for (int j = 0; j < 4; ++j)
                    acc[i][j] += am[i] * bn[j];
        }
    }

    const int n_base = n0 + tx4;
    if (mode != 1) {
        const float* bp2 = bias + n_base;
        float4 bb = make_float4(bp2[0], bp2[1], bp2[2], bp2[3]);
#pragma unroll
        for (int i = 0; i < 8; ++i) {
            int m = m0 + ty8 + i;
            float4 v = make_float4(acc[i][0] + bb.x, acc[i][1] + bb.y,
                                   acc[i][2] + bb.z, acc[i][3] + bb.w);
            *(float4*)(C + (size_t)m * N + n_base) = v;
        }
    } else {
        int t3 = n_base >> 9;            // 0:q 1:k 2:v
        int cc = n_base & 511;
        int h = cc >> 6, hd = cc & 63;
        float* dst = (t3 == 0) ? g_q : (t3 == 1) ? g_k : g_v;
        __nv_bfloat16* dsth = (t3 == 0) ? g_qh : (t3 == 1) ? g_kh : nullptr;
        const float* bp2 = bias + n_base;
        float4 bb = make_float4(bp2[0], bp2[1], bp2[2], bp2[3]);
#pragma unroll
        for (int i = 0; i < 8; ++i) {
            int m = m0 + ty8 + i;
            int b = m >> 11, s = m & 2047;
            size_t off = (((size_t)(b * H_ + h) * S_) + s) * HD_ + hd;
            float v0 = acc[i][0] + bb.x, v1 = acc[i][1] + bb.y;
            float v2 = acc[i][2] + bb.z, v3 = acc[i][3] + bb.w;
            *(float4*)(dst + off) = make_float4(v0, v1, v2, v3);
            if (dsth) {
                unsigned p0 = (unsigned)__bfloat16_as_ushort(__float2bfloat16_rn(v0)) |
                              ((unsigned)__bfloat16_as_ushort(__float2bfloat16_rn(v1)) << 16);
                unsigned p1 = (unsigned)__bfloat16_as_ushort(__float2bfloat16_rn(v2)) |
                              ((unsigned)__bfloat16_as_ushort(__float2bfloat16_rn(v3)) << 16);
                *(uint2*)(dsth + off) = make_uint2(p0, p1);
            }
        }
    }
}

// ---------------------------------------------------------------------------
__global__ void fi_kernel()
{
    int i = blockIdx.x * blockDim.x + threadIdx.x;
    if (i >= NBH * S_) return;
    const float4* q = (const float4*)(g_q + (size_t)i * HD_);
    float s = 0.f;
#pragma unroll
    for (int u = 0; u < 16; ++u) {
        float4 v = q[u];
        s += v.x + v.y + v.z + v.w;
    }
    float mval = s * (1.f / 64.f);
    g_fi[i] = 1.f / (1.f + expf(-mval));
}

// ---------------------------------------------------------------------------
__device__ __forceinline__ void ldsm4(unsigned* r, unsigned saddr)
{
    asm volatile("ldmatrix.sync.aligned.m8n8.x4.shared.b16 {%0,%1,%2,%3}, [%4];"
                 : "=r"(r[0]), "=r"(r[1]), "=r"(r[2]), "=r"(r[3]) : "r"(saddr));
}

__device__ __forceinline__ void mma_bf16(float* c, const unsigned* a, const unsigned* b)
{
    asm volatile("mma.sync.aligned.m16n8k16.row.col.f32.bf16.bf16.f32 "
                 "{%0,%1,%2,%3},{%4,%5,%6,%7},{%8,%9},{%0,%1,%2,%3};"
                 : "+f"(c[0]), "+f"(c[1]), "+f"(c[2]), "+f"(c[3])
                 : "r"(a[0]), "r"(a[1]), "r"(a[2]), "r"(a[3]),
                   "r"(b[0]), "r"(b[1]));
}

// Sequential d-ascending single-accumulator FFMA chain (LOAD-BEARING: exact
// tie resolution matching the reference — do not change).
__device__ __forceinline__ float dot64_seq(const float* __restrict__ a,
                                           const float* __restrict__ b)
{
    const float4* A4 = (const float4*)a;
    const float4* B4 = (const float4*)b;
    float s = 0.f;
#pragma unroll
    for (int i = 0; i < 16; ++i) {
        float4 x = A4[i], y = B4[i];
        s = __fmaf_rn(x.x, y.x, s);
        s = __fmaf_rn(x.y, y.y, s);
        s = __fmaf_rn(x.z, y.z, s);
        s = __fmaf_rn(x.w, y.w, s);
    }
    return s;
}

// sorted-desc top-5 insert (pre-checked by caller: v > tv[4])
__device__ __forceinline__ void ins5(float* tv, int* ti, float v, int idx)
{
    tv[4] = v; ti[4] = idx;
#pragma unroll
    for (int u = 4; u > 0; --u) {
        if (tv[u] > tv[u - 1]) {
            float a = tv[u]; tv[u] = tv[u - 1]; tv[u - 1] = a;
            int   b = ti[u]; ti[u] = ti[u - 1]; ti[u - 1] = b;
        }
    }
}

// ---------------------------------------------------------------------------
// Best-measured attention (160.8us in R15): tensor-core approx scores,
// in-register per-lane top-5 per row -> 20 candidates/row -> EXACT dot64_seq
// rescore -> top-5 -> window mask -> softmax -> attn scatter + sparse ctx.
// No zero-fill here — it rides inside the DRAM-idle QKV GEMM.
// ---------------------------------------------------------------------------
__global__ __launch_bounds__(256)
void attn_mma3(float* __restrict__ out_attn)
{
    __shared__ __align__(16) unsigned char shK[16384];  // 128 keys x 128B swizzled
    __shared__ float mbv[128 * 20];
    __shared__ int   mbi[128 * 20];
    __shared__ float spw[128][5];
    __shared__ unsigned short spidx[128][5];

    const int tid = threadIdx.x;
    const int w = tid >> 5, lane = tid & 31;
    const int bh = blockIdx.y;
    const int qblk = blockIdx.x << 7;

    const __nv_bfloat16* qh = g_qh + ((size_t)bh * S_ + qblk) * HD_;
    const __nv_bfloat16* kh = g_kh + (size_t)bh * S_ * HD_;

    // ---- A fragments for this warp's 16 rows (verified layout) ----
    unsigned Af[4][4];
    {
        int r = (w << 4) + (lane >> 2);
        int c0 = (lane & 3) << 1;
#pragma unroll
        for (int ks = 0; ks < 4; ++ks) {
            Af[ks][0] = *(const unsigned*)(qh + (size_t)r * 64 + ks * 16 + c0);
            Af[ks][1] = *(const unsigned*)(qh + (size_t)(r + 8) * 64 + ks * 16 + c0);
            Af[ks][2] = *(const unsigned*)(qh + (size_t)r * 64 + ks * 16 + c0 + 8);
            Af[ks][3] = *(const unsigned*)(qh + (size_t)(r + 8) * 64 + ks * 16 + c0 + 8);
        }
    }

    float tvA[5], tvB[5]; int tiA[5], tiB[5];
#pragma unroll
    for (int i = 0; i < 5; ++i) {
        tvA[i] = -INFINITY; tvB[i] = -INFINITY; tiA[i] = 0; tiB[i] = 0;
    }

    const int mykey = tid >> 1;
    const int cbase = (tid & 1) << 2;
    uint4 pf[4];
#pragma unroll
    for (int j = 0; j < 4; ++j)
        pf[j] = *(const uint4*)((const char*)kh + (size_t)mykey * 128 + (cbase + j) * 16);

    const int m = lane >> 3, ii = lane & 7;

    for (int kt = 0; kt < 16; ++kt) {
        __syncthreads();
#pragma unroll
        for (int j = 0; j < 4; ++j)
            *(uint4*)(shK + mykey * 128 + (((cbase + j) ^ (mykey & 7)) << 4)) = pf[j];
        __syncthreads();
        if (kt < 15) {
            const char* src = (const char*)kh + ((size_t)(kt + 1) * 128 + mykey) * 128;
#pragma unroll
            for (int j = 0; j < 4; ++j)
                pf[j] = *(const uint4*)(src + (cbase + j) * 16);
        }

#pragma unroll
        for (int np = 0; np < 8; ++np) {
            float c[8];
#pragma unroll
            for (int q = 0; q < 8; ++q) c[q] = 0.f;
#pragma unroll
            for (int ks = 0; ks < 4; ++ks) {
                int keyy = (np << 4) + ((m >> 1) << 3) + ii;
                int ch = (ks << 1) + (m & 1);
                unsigned br[4];
                unsigned sa = (unsigned)__cvta_generic_to_shared(
                    shK + keyy * 128 + ((ch ^ (keyy & 7)) << 4));
                ldsm4(br, sa);
                mma_bf16(c, Af[ks], br);
                mma_bf16(c + 4, Af[ks], br + 2);
            }
            int kb = (kt << 7) + (np << 4) + ((lane & 3) << 1);
            if (c[0] > tvA[4]) ins5(tvA, tiA, c[0], kb);
            if (c[1] > tvA[4]) ins5(tvA, tiA, c[1], kb + 1);
            if (c[2] > tvB[4]) ins5(tvB, tiB, c[2], kb);
            if (c[3] > tvB[4]) ins5(tvB, tiB, c[3], kb + 1);
            if (c[4] > tvA[4]) ins5(tvA, tiA, c[4], kb + 8);
            if (c[5] > tvA[4]) ins5(tvA, tiA, c[5], kb + 9);
            if (c[6] > tvB[4]) ins5(tvB, tiB, c[6], kb + 8);
            if (c[7] > tvB[4]) ins5(tvB, tiB, c[7], kb + 9);
        }
    }

    // ---- dump 5 candidates per (row, lane-group) to smem ----
    {
        int rowA = (w << 4) + (lane >> 2);
        int rowB = rowA + 8;
        int l = lane & 3;
#pragma unroll
        for (int u = 0; u < 5; ++u) {
            mbv[rowA * 20 + l * 5 + u] = tvA[u];
            mbi[rowA * 20 + l * 5 + u] = tiA[u];
            mbv[rowB * 20 + l * 5 + u] = tvB[u];
            mbi[rowB * 20 + l * 5 + u] = tiB[u];
        }
    }
    __syncthreads();

    // ---- exact sequential-fp32 rescore: 2 threads/row, 10 candidates each ----
    const float* kbase = g_k + (size_t)bh * S_ * HD_;
    {
        const int q_own = tid >> 1, par = tid & 1;
        const float* qrow = g_q + ((size_t)bh * S_ + qblk + q_own) * HD_;
#pragma unroll
        for (int i = 0; i < 10; ++i) {
            int slot = q_own * 20 + (par * 2 + (i >= 5 ? 1 : 0)) * 5 + (i % 5);
            mbv[slot] = dot64_seq(qrow, kbase + (size_t)mbi[slot] * HD_);
        }
    }
    __syncthreads();

    // ---- per-row merge of 20, exact top-5, mask, softmax, scatter ----
    if (tid < 128) {
        const int q = tid;
        const int grow = qblk + q;
        float v20[20]; int k20[20];
#pragma unroll
        for (int i = 0; i < 20; ++i) { v20[i] = mbv[q * 20 + i]; k20[i] = mbi[q * 20 + i]; }
#pragma unroll
        for (int s = 0; s < 5; ++s)
#pragma unroll
            for (int i = 19; i > s; --i)
                if (v20[i] > v20[i - 1]) {
                    float a = v20[i]; v20[i] = v20[i - 1]; v20[i - 1] = a;
                    int   b = k20[i]; k20[i] = k20[i - 1]; k20[i - 1] = b;
                }

        const float* qrow = g_q + ((size_t)bh * S_ + grow) * HD_;
        bool kp[5];
#pragma unroll
        for (int i = 0; i < 5; ++i) {
            int c = k20[i];
            int mn = min(grow, c), mx = max(grow, c);
            int ow = mn & ~1; if (ow > 2044) ow = 2044;
            bool keep = true;
            if (mx <= ow + 3) {
                float st0 = dot64_seq(qrow, kbase + (size_t)(ow + 0) * HD_);
                float st1 = dot64_seq(qrow, kbase + (size_t)(ow + 1) * HD_);
                float st2 = dot64_seq(qrow, kbase + (size_t)(ow + 2) * HD_);
                float st3 = dot64_seq(qrow, kbase + (size_t)(ow + 3) * HD_);
                float mn01 = fminf(st0, st1), mx01 = fmaxf(st0, st1);
                float mn23 = fminf(st2, st3), mx23 = fmaxf(st2, st3);
                float thr = fminf(fmaxf(mn01, mn23), fminf(mx01, mx23));
                int ci = c - ow;
                float cv = (ci == 0) ? st0 : (ci == 1) ? st1 : (ci == 2) ? st2 : st3;
                keep = (cv >= thr);
            }
            kp[i] = keep;
        }

        float sm = -INFINITY;
#pragma unroll
        for (int i = 0; i < 5; ++i) if (kp[i]) sm = fmaxf(sm, v20[i]);
        sm *= 0.125f;
        float p[5]; float sum = 0.f;
#pragma unroll
        for (int i = 0; i < 5; ++i) {
            p[i] = kp[i] ? expf(v20[i] * 0.125f - sm) : 0.f;
            sum += p[i];
        }
        float inv = 1.f / sum;
#pragma unroll
        for (int i = 0; i < 5; ++i) {
            if (kp[i]) {
                float pi = p[i] * inv;
                int c = k20[i];
                if (out_attn) out_attn[((size_t)bh * S_ + grow) * S_ + c] = pi;
                spw[q][i] = pi * g_fi[(size_t)bh * S_ + c];
                spidx[q][i] = (unsigned short)c;
            } else {
                spw[q][i] = 0.f;
                spidx[q][i] = 0;
            }
        }
    }
    __syncthreads();

    // ---- sparse ctx: 2 threads/row, 32 dims each ----
    {
        const int row = tid >> 1;
        const int h0 = (tid & 1) << 5;
        float4 a[8];
#pragma unroll
        for (int j = 0; j < 8; ++j) a[j] = make_float4(0.f, 0.f, 0.f, 0.f);
        const float* vb = g_v + (size_t)bh * S_ * HD_;
#pragma unroll
        for (int i = 0; i < 5; ++i) {
            float wv = spw[row][i];
            int c = spidx[row][i];
            const float4* vr = (const float4*)(vb + (size_t)c * 64 + h0);
#pragma unroll
            for (int j = 0; j < 8; ++j) {
                float4 vv = vr[j];
                a[j].x += wv * vv.x; a[j].y += wv * vv.y;
                a[j].z += wv * vv.z; a[j].w += wv * vv.w;
            }
        }
        int b = bh >> 3, hh = bh & 7;
        float* dp = g_ctx + ((size_t)(b * S_) + qblk + row) * D_ + (hh << 6) + h0;
#pragma unroll
        for (int j = 0; j < 8; ++j) ((float4*)dp)[j] = a[j];
    }
}

// ---------------------------------------------------------------------------
// 3xTF32 output projection: out = g_ctx @ w_proj + bias.
// A (ctx) fp32, split in-loop; B preconverted (g_wpP).
// ---------------------------------------------------------------------------
__device__ __forceinline__ void mma_tf32(float* c, const unsigned* a, const unsigned* b)
{
    asm volatile("mma.sync.aligned.m16n8k8.row.col.f32.tf32.tf32.f32 "
                 "{%0,%1,%2,%3},{%4,%5,%6,%7},{%8,%9},{%0,%1,%2,%3};"
                 : "+f"(c[0]), "+f"(c[1]), "+f"(c[2]), "+f"(c[3])
                 : "r"(a[0]), "r"(a[1]), "r"(a[2]), "r"(a[3]),
                   "r"(b[0]), "r"(b[1]));
}

__global__ __launch_bounds__(256)
void proj_tf32(const float* __restrict__ bias, float* __restrict__ C)
{
    __shared__ float As[128 * 36];   // [m][k] fp32, pad 36
    __shared__ uint2 Bs[32 * 72];    // [k][n] packed hi/lo, pad 72

    const int tid = threadIdx.x;
    const int lane = tid & 31, w = tid >> 5;
    const int wm = w >> 1, wn = w & 1;
    const int m0 = blockIdx.y << 7, n0 = blockIdx.x << 6;
    const int gr = lane >> 2, gc = lane & 3;

    float acc[2][4][4];
#pragma unroll
    for (int a = 0; a < 2; ++a)
#pragma unroll
        for (int b = 0; b < 4; ++b)
#pragma unroll
            for (int cj = 0; cj < 4; ++cj) acc[a][b][cj] = 0.f;

    const int arow = tid >> 1, ak = (tid & 1) << 4;
    const int brow = tid >> 3, bn = (tid & 7) << 3;

    for (int kc = 0; kc < 512; kc += 32) {
        __syncthreads();
        {
            const float* Ap = g_ctx + (size_t)(m0 + arow) * 512 + kc + ak;
            *(float4*)&As[arow * 36 + ak + 0]  = *(const float4*)(Ap);
            *(float4*)&As[arow * 36 + ak + 4]  = *(const float4*)(Ap + 4);
            *(float4*)&As[arow * 36 + ak + 8]  = *(const float4*)(Ap + 8);
            *(float4*)&As[arow * 36 + ak + 12] = *(const float4*)(Ap + 12);
            const uint4* bg = (const uint4*)(g_wpP + (size_t)(kc + brow) * 512 + n0 + bn);
            uint4* bs = (uint4*)(Bs + brow * 72 + bn);
            bs[0] = bg[0]; bs[1] = bg[1]; bs[2] = bg[2]; bs[3] = bg[3];
        }
        __syncthreads();

#pragma unroll
        for (int kk = 0; kk < 4; ++kk) {
            unsigned ah[2][4], al[2][4];
#pragma unroll
            for (int mt = 0; mt < 2; ++mt) {
                int mrow = (wm << 5) + (mt << 4);
                float a_0 = As[(mrow + gr) * 36 + (kk << 3) + gc];
                float a_1 = As[(mrow + gr + 8) * 36 + (kk << 3) + gc];
                float a_2 = As[(mrow + gr) * 36 + (kk << 3) + gc + 4];
                float a_3 = As[(mrow + gr + 8) * 36 + (kk << 3) + gc + 4];
                tf32split(a_0, ah[mt][0], al[mt][0]);
                tf32split(a_1, ah[mt][1], al[mt][1]);
                tf32split(a_2, ah[mt][2], al[mt][2]);
                tf32split(a_3, ah[mt][3], al[mt][3]);
            }
            unsigned bhv[4][2], blv[4][2];
#pragma unroll
            for (int nt = 0; nt < 4; ++nt) {
                int ncol = (wn << 5) + (nt << 3) + gr;
                uint2 b0 = Bs[((kk << 3) + gc) * 72 + ncol];
                uint2 b1 = Bs[((kk << 3) + gc + 4) * 72 + ncol];
                bhv[nt][0] = b0.x; blv[nt][0] = b0.y;
                bhv[nt][1] = b1.x; blv[nt][1] = b1.y;
            }
#pragma unroll
            for (int mt = 0; mt < 2; ++mt)
#pragma unroll
                for (int nt = 0; nt < 4; ++nt) {
                    mma_tf32(acc[mt][nt], al[mt], bhv[nt]);   // lo*hi
                    mma_tf32(acc[mt][nt], ah[mt], blv[nt]);   // hi*lo
                    mma_tf32(acc[mt][nt], ah[mt], bhv[nt]);   // hi*hi
                }
        }
    }

#pragma unroll
    for (int mt = 0; mt < 2; ++mt)
#pragma unroll
        for (int nt = 0; nt < 4; ++nt) {
            int row = m0 + (wm << 5) + (mt << 4) + gr;
            int col = n0 + (wn << 5) + (nt << 3) + (gc << 1);
            float b0v = bias[col], b1v = bias[col + 1];
            *(float2*)(C + (size_t)row * 512 + col) =
                make_float2(acc[mt][nt][0] + b0v, acc[mt][nt][1] + b1v);
            *(float2*)(C + (size_t)(row + 8) * 512 + col) =
                make_float2(acc[mt][nt][2] + b0v, acc[mt][nt][3] + b1v);
        }
}

// ---------------------------------------------------------------------------
extern "C" void kernel_launch(void* const* d_in, const int* in_sizes, int n_in,
                              void* d_out, int out_size)
{
    const float* x      = (const float*)d_in[0];
    const float* w_qkv  = (const float*)d_in[1];
    const float* b_qkv  = (const float*)d_in[2];
    const float* w_proj = (const float*)d_in[3];
    const float* b_proj = (const float*)d_in[4];
    float* out = (float*)d_out;

    const size_t nproj = (size_t)B_ * S_ * D_;
    const size_t nattn = (size_t)NBH * S_ * S_;
    float* out_attn = ((size_t)out_size >= nproj + nattn) ? (out + nproj) : nullptr;

    // 0) pack w_proj to tf32 hi/lo
    pack_wp<<<256, 256>>>(w_proj);
    // 1) fused QKV projection (FROZEN fp32 numerics) + background zero-fill
    //    of the attn plane (written exactly once across the 2-D grid)
    sgemm_pipe<<<dim3(24, 32), 256>>>(x, w_qkv, b_qkv, nullptr,
                                      B_ * S_, 3 * D_, D_, 1, out_attn);
    // 2) feature importance per (b,h,s)
    fi_kernel<<<128, 256>>>();
    // 3) tensor-core scores / exact top-5 / mask / softmax / sparse ctx
    attn_mma3<<<dim3(S_ / 128, NBH), 256>>>(out_attn);
    // 4) output projection (3xTF32; B preconverted)
    proj_tf32<<<dim3(8, 32), 256>>>(b_proj, out);
}